// round 5
// baseline (speedup 1.0000x reference)
#include <cuda_runtime.h>
#include <cuda_bf16.h>
#include <cstdint>

#define BATCH 2048
#define SEQ   128
#define FEAT  64
#define HID   512
#define NGATE 2048          // 4*HID, gate-interleaved: n = 4*j + g
#define TM    128
#define TN    128
#define TK    16            // K elems per pipeline stage
#define NSTG  4
#define NTH   256

// smem stage layout: rows of 32B data padded to 48B (bank pattern r*12 mod 32 -> conflict-free ldmatrix)
#define PB       48
#define SEG      6144       // 128 rows * 48B  (A_HI | A_MID | B_HI | B_MID each)
#define STAGE    (4 * SEG)  // 24576
#define BIAS_OFF (NSTG * STAGE)         // 98304
#define SMEM_DYN (BIAS_OFF + 512 + 16)

// ---------------- static device buffers (~105 MB) ----------------
__device__ __nv_bfloat16 g_U1h[NGATE * HID],  g_U1m[NGATE * HID];
__device__ __nv_bfloat16 g_W1h[NGATE * FEAT], g_W1m[NGATE * FEAT];
__device__ __nv_bfloat16 g_U2h[NGATE * HID],  g_U2m[NGATE * HID];
__device__ __nv_bfloat16 g_W2h[NGATE * HID],  g_W2m[NGATE * HID];
__device__ __nv_bfloat16 g_xh[(size_t)BATCH * SEQ * FEAT], g_xm[(size_t)BATCH * SEQ * FEAT];
__device__ __nv_bfloat16 g_h1h[2][BATCH * HID], g_h1m[2][BATCH * HID];
__device__ __nv_bfloat16 g_h2h[2][BATCH * HID], g_h2m[2][BATCH * HID];
__device__ float g_c1[BATCH * HID], g_c2[BATCH * HID];
__device__ float g_b1i[NGATE], g_b2i[NGATE];

// ---------------- PTX helpers (baseline sm_80/90 features only) ----------------
__device__ __forceinline__ uint32_t smem_u32(const void* p) {
    uint32_t a;
    asm("{ .reg .u64 t; cvta.to.shared.u64 t, %1; cvt.u32.u64 %0, t; }" : "=r"(a) : "l"(p));
    return a;
}
__device__ __forceinline__ void cpa(uint32_t dst, const void* src) {
    asm volatile("cp.async.cg.shared.global [%0], [%1], 16;" :: "r"(dst), "l"(src));
}
__device__ __forceinline__ void cp_commit() { asm volatile("cp.async.commit_group;"); }
template <int N> __device__ __forceinline__ void cp_wait() {
    asm volatile("cp.async.wait_group %0;" :: "n"(N));
}
__device__ __forceinline__ void ldm4(uint32_t* r, uint32_t addr) {
    asm volatile("ldmatrix.sync.aligned.m8n8.x4.shared.b16 {%0,%1,%2,%3}, [%4];"
        : "=r"(r[0]), "=r"(r[1]), "=r"(r[2]), "=r"(r[3]) : "r"(addr));
}
__device__ __forceinline__ void mma16816(float* c, const uint32_t* a, const uint32_t* b) {
    asm volatile("mma.sync.aligned.m16n8k16.row.col.f32.bf16.bf16.f32 "
        "{%0,%1,%2,%3}, {%4,%5,%6,%7}, {%8,%9}, {%0,%1,%2,%3};"
        : "+f"(c[0]), "+f"(c[1]), "+f"(c[2]), "+f"(c[3])
        : "r"(a[0]), "r"(a[1]), "r"(a[2]), "r"(a[3]), "r"(b[0]), "r"(b[1]));
}
__device__ __forceinline__ float sigmoid_(float v) { return 1.0f / (1.0f + __expf(-v)); }

// ---------------- fused LSTM step: bf16x3 HMMA GEMM + cell ----------------
__global__ __launch_bounds__(NTH, 2) void lstm_mma(
    const __nv_bfloat16* __restrict__ hph, const __nv_bfloat16* __restrict__ hpm,
    const __nv_bfloat16* __restrict__ Uh,  const __nv_bfloat16* __restrict__ Um, int nRec,
    const __nv_bfloat16* __restrict__ xh,  const __nv_bfloat16* __restrict__ xm, int ldxA,
    const __nv_bfloat16* __restrict__ Wh,  const __nv_bfloat16* __restrict__ Wm, int ldBin, int nIn,
    const float* __restrict__ bint, float* __restrict__ cst,
    __nv_bfloat16* __restrict__ hoh, __nv_bfloat16* __restrict__ hom, int first)
{
    extern __shared__ char smem[];
    const uint32_t sm_base = smem_u32(smem);
    float* biasS = reinterpret_cast<float*>(smem + BIAS_OFF);

    const int tid  = threadIdx.x;
    const int wid  = tid >> 5;
    const int lane = tid & 31;
    const int wm   = wid >> 2;      // 0..1 (M)
    const int wn   = wid & 3;       // 0..3 (N)
    const int m0   = blockIdx.x * TM;
    const int n0   = blockIdx.y * TN;

    if (tid < TN) biasS[tid] = bint[n0 + tid];

    // ldmatrix per-lane addressing (within-stage byte offsets), pitch PB=48
    const int rA  = lane & 15;                 // A rows 0..15 within 16-row tile
    const int kbA = (lane >> 4) * 16;          // k half (bytes)
    const int rB  = (lane & 7) + ((lane >> 4) & 1) * 8;   // B n-rows 0..15
    const int kbB = ((lane >> 3) & 1) * 16;    // k half (bytes)
    const uint32_t aoff = 0 * SEG + (uint32_t)(wm * 64 + rA) * PB + kbA;
    const uint32_t boff = 2 * SEG + (uint32_t)(wn * 32 + rB) * PB + kbB;

    float acc[4][4][4];
    #pragma unroll
    for (int a = 0; a < 4; ++a)
        #pragma unroll
        for (int b = 0; b < 4; ++b)
            #pragma unroll
            for (int c = 0; c < 4; ++c) acc[a][b][c] = 0.0f;

    const int nb = nRec + nIn;

    auto stage_load = [&](int it, int s) {
        const __nv_bfloat16 *Ah, *Am, *Bh, *Bm; int lda, ldb, k0;
        if (it < nRec) { Ah = hph; Am = hpm; lda = HID;  Bh = Uh; Bm = Um; ldb = HID;   k0 = it * TK; }
        else           { Ah = xh;  Am = xm;  lda = ldxA; Bh = Wh; Bm = Wm; ldb = ldBin; k0 = (it - nRec) * TK; }
        const uint32_t sb = sm_base + (uint32_t)s * STAGE;
        #pragma unroll
        for (int i = 0; i < 4; ++i) {                       // 1024 16B tasks / 256 thr
            int e = tid + i * NTH;
            int seg = e >> 8;                               // 0 Ahi, 1 Amid, 2 Bhi, 3 Bmid
            int r = (e >> 1) & 127, c = e & 1;
            uint32_t d = sb + (uint32_t)seg * SEG + (uint32_t)r * PB + c * 16;
            const __nv_bfloat16* src;
            if (seg == 0)      src = Ah + (size_t)(m0 + r) * lda + k0 + c * 8;
            else if (seg == 1) src = Am + (size_t)(m0 + r) * lda + k0 + c * 8;
            else if (seg == 2) src = Bh + (size_t)(n0 + r) * ldb + k0 + c * 8;
            else               src = Bm + (size_t)(n0 + r) * ldb + k0 + c * 8;
            cpa(d, src);
        }
    };

    // preload NSTG-1 = 3 stages
    #pragma unroll
    for (int s = 0; s < NSTG - 1; ++s) {
        if (s < nb) stage_load(s, s);
        cp_commit();
    }

    for (int it = 0; it < nb; ++it) {
        cp_wait<NSTG - 2>();        // stage it landed
        __syncthreads();            // visibility + all warps done with stage it-1
        if (it + NSTG - 1 < nb) stage_load(it + NSTG - 1, (it + NSTG - 1) & (NSTG - 1));
        cp_commit();

        const uint32_t sb = sm_base + (uint32_t)(it & (NSTG - 1)) * STAGE;
        uint32_t bh[2][4], bm[2][4];
        #pragma unroll
        for (int p = 0; p < 2; ++p) {
            uint32_t ba = sb + boff + (uint32_t)p * (16 * PB);
            ldm4(bh[p], ba);
            ldm4(bm[p], ba + SEG);
        }
        #pragma unroll
        for (int mi = 0; mi < 4; ++mi) {
            uint32_t ah[4], am[4];
            uint32_t aa = sb + aoff + (uint32_t)mi * (16 * PB);
            ldm4(ah, aa);
            ldm4(am, aa + SEG);
            #pragma unroll
            for (int ni = 0; ni < 4; ++ni) {
                const uint32_t* bhp = &bh[ni >> 1][(ni & 1) * 2];
                const uint32_t* bmp = &bm[ni >> 1][(ni & 1) * 2];
                mma16816(acc[mi][ni], ah, bhp);
                mma16816(acc[mi][ni], am, bhp);
                mma16816(acc[mi][ni], ah, bmp);
            }
        }
    }

    // ---------------- epilogue: bias + gate exchange + fused cell ----------------
    const int jbase = (n0 >> 2) + wn * 8;
    #pragma unroll
    for (int mi = 0; mi < 4; ++mi) {
        #pragma unroll
        for (int ni = 0; ni < 4; ++ni) {
            const int nl = wn * 32 + ni * 8 + (lane & 3) * 2;
            const float bb0 = biasS[nl], bb1 = biasS[nl + 1];
            #pragma unroll
            for (int r = 0; r < 2; ++r) {
                float v0 = acc[mi][ni][r * 2 + 0] + bb0;
                float v1 = acc[mi][ni][r * 2 + 1] + bb1;
                float o0 = __shfl_xor_sync(0xffffffffu, v0, 1);
                float o1 = __shfl_xor_sync(0xffffffffu, v1, 1);
                if ((lane & 1) == 0) {
                    const int m = m0 + wm * 64 + mi * 16 + (lane >> 2) + r * 8;
                    const int j = jbase + ni * 2 + ((lane & 3) >> 1);
                    const size_t idx = (size_t)m * HID + j;
                    float cp = first ? 0.0f : cst[idx];
                    float iv = sigmoid_(v0), fv = sigmoid_(v1);
                    float ci = fmaxf(o0, 0.0f), ov = sigmoid_(o1);
                    float cn = fv * cp + iv * ci;
                    cst[idx] = cn;
                    float hv = ov * fmaxf(cn, 0.0f);
                    __nv_bfloat16 hh = __float2bfloat16(hv);
                    hoh[idx] = hh;
                    hom[idx] = __float2bfloat16(hv - __bfloat162float(hh));
                }
            }
        }
    }
}

// ---------------- prep (merged to 3 launches so ncu -s 5 hits steady-state lstm_mma) ----------------
__global__ void prep_weights_all(const float* __restrict__ U1, const float* __restrict__ W1,
                                 const float* __restrict__ U2, const float* __restrict__ W2,
                                 __nv_bfloat16* __restrict__ U1h, __nv_bfloat16* __restrict__ U1m,
                                 __nv_bfloat16* __restrict__ W1h, __nv_bfloat16* __restrict__ W1m,
                                 __nv_bfloat16* __restrict__ U2h, __nv_bfloat16* __restrict__ U2m,
                                 __nv_bfloat16* __restrict__ W2h, __nv_bfloat16* __restrict__ W2m)
{
    const int NU = NGATE * HID, NW = NGATE * FEAT;
    int idx = blockIdx.x * blockDim.x + threadIdx.x;
    const float* src; __nv_bfloat16 *dh, *dm; int K, li;
    if (idx < NU)                    { src = U1; dh = U1h; dm = U1m; K = HID;  li = idx; }
    else if (idx < NU + NW)          { src = W1; dh = W1h; dm = W1m; K = FEAT; li = idx - NU; }
    else if (idx < 2 * NU + NW)      { src = U2; dh = U2h; dm = U2m; K = HID;  li = idx - NU - NW; }
    else if (idx < 3 * NU + NW)      { src = W2; dh = W2h; dm = W2m; K = HID;  li = idx - 2 * NU - NW; }
    else return;
    int n = li / K, k = li - n * K;
    int col = (n & 3) * HID + (n >> 2);          // gate-interleave: n = 4j+g
    float v = src[(size_t)k * NGATE + col];
    __nv_bfloat16 h = __float2bfloat16(v);
    dh[li] = h;
    dm[li] = __float2bfloat16(v - __bfloat162float(h));
}

__global__ void prep_bias(const float* __restrict__ b1, const float* __restrict__ b2,
                          float* __restrict__ d1, float* __restrict__ d2)
{
    int n = blockIdx.x * blockDim.x + threadIdx.x;
    if (n >= NGATE) return;
    int col = (n & 3) * HID + (n >> 2);
    d1[n] = b1[col];
    d2[n] = b2[col];
}

__global__ void prep_x(const float* __restrict__ x, __nv_bfloat16* __restrict__ xh,
                       __nv_bfloat16* __restrict__ xm, int n)
{
    int i = blockIdx.x * blockDim.x + threadIdx.x;
    if (i >= n) return;
    float v = x[i];
    __nv_bfloat16 h = __float2bfloat16(v);
    xh[i] = h;
    xm[i] = __float2bfloat16(v - __bfloat162float(h));
}

// ---------------- dense head: out[b] = (h2hi+h2mid) @ Wd + bd ----------------
__global__ __launch_bounds__(256) void dense_kernel(
    const __nv_bfloat16* __restrict__ hh, const __nv_bfloat16* __restrict__ hm,
    const float* __restrict__ Wd, const float* __restrict__ bd, float* __restrict__ out)
{
    int b = blockIdx.x * 8 + (threadIdx.x >> 5);
    int lane = threadIdx.x & 31;
    const __nv_bfloat16* rh = hh + (size_t)b * HID;
    const __nv_bfloat16* rm = hm + (size_t)b * HID;
    float s = 0.0f;
    #pragma unroll
    for (int k = lane; k < HID; k += 32)
        s += (__bfloat162float(rh[k]) + __bfloat162float(rm[k])) * Wd[k];
    #pragma unroll
    for (int o = 16; o > 0; o >>= 1) s += __shfl_xor_sync(0xffffffffu, s, o);
    if (lane == 0) out[b] = s + bd[0];
}

extern "C" void kernel_launch(void* const* d_in, const int* in_sizes, int n_in,
                              void* d_out, int out_size)
{
    const float* x  = (const float*)d_in[0];
    const float* W1 = (const float*)d_in[1];
    const float* U1 = (const float*)d_in[2];
    const float* b1 = (const float*)d_in[3];
    const float* W2 = (const float*)d_in[4];
    const float* U2 = (const float*)d_in[5];
    const float* b2 = (const float*)d_in[6];
    const float* Wd = (const float*)d_in[7];
    const float* bd = (const float*)d_in[8];
    float* out = (float*)d_out;

    cudaFuncSetAttribute(lstm_mma, cudaFuncAttributeMaxDynamicSharedMemorySize, SMEM_DYN);

    __nv_bfloat16 *U1h, *U1m, *W1h, *W1m, *U2h, *U2m, *W2h, *W2m, *xh, *xm;
    __nv_bfloat16 *h1h, *h1m, *h2h, *h2m;
    float *c1, *c2, *b1i, *b2i;
    cudaGetSymbolAddress((void**)&U1h, g_U1h); cudaGetSymbolAddress((void**)&U1m, g_U1m);
    cudaGetSymbolAddress((void**)&W1h, g_W1h); cudaGetSymbolAddress((void**)&W1m, g_W1m);
    cudaGetSymbolAddress((void**)&U2h, g_U2h); cudaGetSymbolAddress((void**)&U2m, g_U2m);
    cudaGetSymbolAddress((void**)&W2h, g_W2h); cudaGetSymbolAddress((void**)&W2m, g_W2m);
    cudaGetSymbolAddress((void**)&xh,  g_xh);  cudaGetSymbolAddress((void**)&xm,  g_xm);
    cudaGetSymbolAddress((void**)&h1h, g_h1h); cudaGetSymbolAddress((void**)&h1m, g_h1m);
    cudaGetSymbolAddress((void**)&h2h, g_h2h); cudaGetSymbolAddress((void**)&h2m, g_h2m);
    cudaGetSymbolAddress((void**)&c1,  g_c1);  cudaGetSymbolAddress((void**)&c2,  g_c2);
    cudaGetSymbolAddress((void**)&b1i, g_b1i); cudaGetSymbolAddress((void**)&b2i, g_b2i);

    __nv_bfloat16* h1hb[2] = {h1h, h1h + BATCH * HID};
    __nv_bfloat16* h1mb[2] = {h1m, h1m + BATCH * HID};
    __nv_bfloat16* h2hb[2] = {h2h, h2h + BATCH * HID};
    __nv_bfloat16* h2mb[2] = {h2m, h2m + BATCH * HID};

    {
        int ntot = 3 * NGATE * HID + NGATE * FEAT;
        prep_weights_all<<<(ntot + 255) / 256, 256>>>(U1, W1, U2, W2,
            U1h, U1m, W1h, W1m, U2h, U2m, W2h, W2m);
        prep_bias<<<(NGATE + 255) / 256, 256>>>(b1, b2, b1i, b2i);
        int nx = BATCH * SEQ * FEAT;
        prep_x<<<(nx + 255) / 256, 256>>>(x, xh, xm, nx);
    }

    dim3 grid(BATCH / TM, NGATE / TN);   // 16 x 16 = 256 CTAs

    for (int t = 0; t < SEQ; ++t) {
        int pv = (t - 1) & 1, cu = t & 1;
        lstm_mma<<<grid, NTH, SMEM_DYN>>>(
            t ? h1hb[pv] : nullptr, t ? h1mb[pv] : nullptr, U1h, U1m, t ? (HID / TK) : 0,
            xh + (size_t)t * FEAT, xm + (size_t)t * FEAT, SEQ * FEAT,
            W1h, W1m, FEAT, FEAT / TK,
            b1i, c1, h1hb[cu], h1mb[cu], t == 0);
        lstm_mma<<<grid, NTH, SMEM_DYN>>>(
            t ? h2hb[pv] : nullptr, t ? h2mb[pv] : nullptr, U2h, U2m, t ? (HID / TK) : 0,
            h1hb[cu], h1mb[cu], HID,
            W2h, W2m, HID, HID / TK,
            b2i, c2, h2hb[cu], h2mb[cu], t == 0);
    }

    dense_kernel<<<BATCH / 8, 256>>>(h2hb[(SEQ - 1) & 1], h2mb[(SEQ - 1) & 1], Wd, bd, out);
}